// round 1
// baseline (speedup 1.0000x reference)
#include <cuda_runtime.h>
#include <math.h>

#define FEAT   64
#define EMBC   256
#define IMGSZ  1024
#define NCELLS 256
#define THRESH 0.65f

// ---------------- device scratch (no allocations allowed) ----------------
__device__ float d_sim[FEAT * FEAT];
__device__ float d_P[1024 * 1024];           // cropped intermediate (ph x pw), max 1024x1024
__device__ float4 d_xtab[4096];              // per-output-x interp: {i0 (bitcast), w0, w1, 0}
__device__ unsigned long long d_minkey;      // global argmin key
__device__ unsigned long long d_cellkey[NCELLS];

// ---------------- ordered-float key helpers ----------------
__device__ __forceinline__ unsigned fkey(float f) {
    unsigned u = __float_as_uint(f);
    return (u >> 31) ? ~u : (u | 0x80000000u);   // monotone: smaller float -> smaller key
}
__device__ __forceinline__ float unfkey(unsigned k) {
    return (k & 0x80000000u) ? __uint_as_float(k & 0x7FFFFFFFu) : __uint_as_float(~k);
}

// ---------------- jax.image.resize (linear, antialias=False) fp-exact taps ----------------
struct Tap { int i0; float w0, w1; };

// sample = (o + 0.5) * (1/scale) - 0.5, all fp32, mul then sub (no fma) — matches jax
__device__ __forceinline__ float samplef(int o, float inv) {
    return __fsub_rn(__fmul_rn(__fadd_rn((float)o, 0.5f), inv), 0.5f);
}

// Taps (i0, i0+1) with weights; edges collapse to a single exact-weight-1 tap,
// matching jax's drop-out-of-range + renormalize behavior (value == edge pixel exactly).
__device__ __forceinline__ Tap make_tap(float s, int n) {
    Tap t;
    float fs = floorf(s);
    int i0 = (int)fs;
    if (i0 < 0)            { t.i0 = 0;     t.w0 = 1.f; t.w1 = 0.f; }
    else if (i0 >= n - 1)  { t.i0 = n - 2; t.w0 = 0.f; t.w1 = 1.f; }
    else {
        // jax: w_k = 1 - |s - k| for k = i0, i0+1, then normalize by the sum
        float w0  = __fsub_rn(1.0f, __fsub_rn(s, fs));
        float w1  = __fsub_rn(1.0f, __fsub_rn((float)(i0 + 1), s));
        float sum = __fadd_rn(w0, w1);
        if (sum != 1.0f) { w0 = __fdiv_rn(w0, sum); w1 = __fdiv_rn(w1, sum); }
        t.i0 = i0; t.w0 = w0; t.w1 = w1;
    }
    return t;
}

// ---------------- kernel 1: sim = ref . (emb / ||emb||_c), plus reduction-state init ----------------
__global__ void k_sim(const float* __restrict__ emb, const float* __restrict__ ref) {
    int p = blockIdx.x * blockDim.x + threadIdx.x;
    if (blockIdx.x == 0) {
        if (threadIdx.x == 0) d_minkey = ~0ull;
        if (threadIdx.x < NCELLS) d_cellkey[threadIdx.x] = 0ull;
    }
    if (p < FEAT * FEAT) {
        float dot = 0.f, nrm = 0.f;
        #pragma unroll 8
        for (int c = 0; c < EMBC; c++) {
            float e = emb[c * (FEAT * FEAT) + p];   // coalesced across p
            dot = fmaf(ref[c], e, dot);
            nrm = fmaf(e, e, nrm);
        }
        d_sim[p] = dot / sqrtf(nrm);
    }
}

// ---------------- kernel 2: build P (first resize 64->1024, cropped to ph x pw) + x-table ----------------
__global__ void k_prep(const int* __restrict__ ori) {
    int H = ori[0], W = ori[1];
    int mx = max(H, W);
    double scale = (double)IMGSZ / (double)mx;
    int ph = (int)floor((double)H * scale + 0.5);
    int pw = (int)floor((double)W * scale + 0.5);
    float invx = (float)(1.0 / ((double)W / (double)pw));   // 1/(out/in), rounded to fp32 like jax

    int idx = blockIdx.x * blockDim.x + threadIdx.x;

    // per-output-x interpolation table for the second resize
    if (idx < W && idx < 4096) {
        Tap t = make_tap(samplef(idx, invx), pw);
        d_xtab[idx] = make_float4(__int_as_float(t.i0), t.w0, t.w1, 0.f);
    }

    const float inv1 = 0.0625f;   // 1/16 exact (64 -> 1024)
    int tot = ph * pw;
    for (int p = idx; p < tot; p += gridDim.x * blockDim.x) {
        int yy = p / pw, xx = p - yy * pw;
        Tap ty = make_tap(samplef(yy, inv1), FEAT);
        Tap tx = make_tap(samplef(xx, inv1), FEAT);
        const float* r0 = d_sim + ty.i0 * FEAT;
        float a = r0[tx.i0],        b = r0[tx.i0 + 1];
        float c = r0[FEAT + tx.i0], d = r0[FEAT + tx.i0 + 1];
        // y-contraction first, then x (matches einsum path), fma accumulation
        float c0 = fmaf(ty.w1, c, __fmul_rn(ty.w0, a));
        float c1 = fmaf(ty.w1, d, __fmul_rn(ty.w0, b));
        d_P[p]   = fmaf(tx.w1, c1, __fmul_rn(tx.w0, c0));
    }
}

// ---------------- kernel 3: scan all H x W pixels: argmin + thresholded per-cell argmax ----------------
__global__ void __launch_bounds__(256) k_scan(const int* __restrict__ ori) {
    int H = ori[0], W = ori[1];
    int mx = max(H, W);
    double scale = (double)IMGSZ / (double)mx;
    int ph = (int)floor((double)H * scale + 0.5);
    int pw = (int)floor((double)W * scale + 0.5);
    float invy = (float)(1.0 / ((double)H / (double)ph));
    float r64  = (float)(scale / 64.0);   // ratio / DOWNSIZING, rounded to fp32 like jnp

    unsigned long long localkey = ~0ull;

    for (int y = blockIdx.x; y < H; y += gridDim.x) {
        Tap ty = make_tap(samplef(y, invy), ph);
        const float* __restrict__ R0 = d_P + ty.i0 * pw;
        const float* __restrict__ R1 = R0 + pw;
        float wy0 = ty.w0, wy1 = ty.w1;
        int gy16 = 16 * (int)floorf(__fmul_rn((float)y, r64));
        int base = y * W;

        float rbest = INFINITY; int rbidx = 0;
        for (int x = threadIdx.x; x < W; x += blockDim.x) {
            float4 tx = d_xtab[x];
            int x0 = __float_as_int(tx.x);
            float c0 = fmaf(wy1, R1[x0],     __fmul_rn(wy0, R0[x0]));
            float c1 = fmaf(wy1, R1[x0 + 1], __fmul_rn(wy0, R0[x0 + 1]));
            float v  = fmaf(tx.z, c1, __fmul_rn(tx.y, c0));

            if (v < rbest) { rbest = v; rbidx = base + x; }   // strict <: keeps earliest idx

            if (v > THRESH) {  // extremely rare with this data; exact semantics preserved
                int cell = gy16 + (int)floorf(__fmul_rn((float)x, r64));
                unsigned long long ck = ((unsigned long long)fkey(v) << 32)
                                      | (unsigned)(0xFFFFFFFFu - (unsigned)(base + x));
                atomicMax(&d_cellkey[cell], ck);   // max value, then lowest index
            }
        }
        unsigned long long k = ((unsigned long long)fkey(rbest) << 32) | (unsigned)rbidx;
        localkey = min(localkey, k);
    }

    __shared__ unsigned long long sk[256];
    sk[threadIdx.x] = localkey;
    __syncthreads();
    for (int o = 128; o > 0; o >>= 1) {
        if (threadIdx.x < o) sk[threadIdx.x] = min(sk[threadIdx.x], sk[threadIdx.x + o]);
        __syncthreads();
    }
    if (threadIdx.x == 0) atomicMin(&d_minkey, sk[0]);
}

// ---------------- kernel 4: build points, stable-sort by score desc, write output ----------------
__global__ void k_final(const int* __restrict__ ori, float* __restrict__ out) {
    int W = ori[1];
    int t = threadIdx.x;   // one thread per cell, 256 threads
    __shared__ float s_key[NCELLS];

    unsigned long long ck = d_cellkey[t];
    bool valid = (ck != 0ull);
    float ps = 0.f; int pidx = 0;
    if (valid) {
        ps   = unfkey((unsigned)(ck >> 32));
        pidx = (int)(0xFFFFFFFFu - (unsigned)(ck & 0xFFFFFFFFull));
    }
    float skey = valid ? ps : -INFINITY;
    s_key[t] = skey;
    __syncthreads();

    // stable descending rank (ties -> lower cell index first), matches jnp.argsort(-key)
    int rank = 0;
    for (int j = 0; j < NCELLS; j++) {
        float o = s_key[j];
        rank += (o > skey) || (o == skey && j < t);
    }

    float px = valid ? (float)(pidx % W) : -1.f;
    float py = valid ? (float)(pidx / W) : -1.f;
    float pv = valid ? ps : -1.f;
    out[rank * 3 + 0] = px;
    out[rank * 3 + 1] = py;
    out[rank * 3 + 2] = pv;

    if (t == 0) {
        unsigned long long mk = d_minkey;
        unsigned bidx = (unsigned)(mk & 0xFFFFFFFFull);
        out[NCELLS * 3 + 0] = (float)(bidx % (unsigned)W);   // bg col (x)
        out[NCELLS * 3 + 1] = (float)(bidx / (unsigned)W);   // bg row (y)
    }
}

// ---------------- launch ----------------
extern "C" void kernel_launch(void* const* d_in, const int* in_sizes, int n_in,
                              void* d_out, int out_size) {
    // identify inputs by element count for robustness
    int ie = 0, ir = 1, io = 2;
    for (int i = 0; i < n_in; i++) {
        if (in_sizes[i] == 2) io = i;
        else if (in_sizes[i] == EMBC) ir = i;
        else ie = i;
    }
    const float* emb = (const float*)d_in[ie];
    const float* ref = (const float*)d_in[ir];
    const int*   ori = (const int*)d_in[io];
    float* out = (float*)d_out;

    k_sim <<<16,   256>>>(emb, ref);
    k_prep<<<2304, 256>>>(ori);
    k_scan<<<2160, 256>>>(ori);
    k_final<<<1,   256>>>(ori, out);
}